// round 5
// baseline (speedup 1.0000x reference)
#include <cuda_runtime.h>
#include <math.h>

#define NBATCH 1024
#define NSEQ   200
#define NROWS  (NBATCH*NSEQ)   /* 204800 */

/* ------------ static scratch (no allocations allowed) ------------ */
__device__ float g_enc [NROWS*128];           /* encoder output                    */
__device__ float g_xpre[NROWS*1024];          /* gate preacts, [r][h8*128 + u*4+g] */
__device__ float g_hseq[NSEQ*NBATCH*256];     /* hx per step (output GEMM input)   */
__device__ float g_predpart[2][8*NBATCH*2];   /* parity-buffered pred partials     */

typedef unsigned long long u64;

__device__ __forceinline__ u64 pack2(float lo, float hi){
    u64 r; asm("mov.b64 %0,{%1,%2};" : "=l"(r) : "f"(lo), "f"(hi)); return r;
}
__device__ __forceinline__ void unpack2(u64 v, float& lo, float& hi){
    asm("mov.b64 {%0,%1},%2;" : "=f"(lo), "=f"(hi) : "l"(v));
}
__device__ __forceinline__ u64 fma2(u64 a, u64 b, u64 c){
    u64 d; asm("fma.rn.f32x2 %0,%1,%2,%3;" : "=l"(d) : "l"(a), "l"(b), "l"(c)); return d;
}
__device__ __forceinline__ float sigmoidf_(float x){
    return __fdividef(1.0f, 1.0f + __expf(-x));
}

/* ================= Kernel 1: per-(b,t) set encoder ================= */
__global__ void enc_kernel(const float* __restrict__ coords,
                           const float* __restrict__ W_e1, const float* __restrict__ b_e1,
                           const float* __restrict__ W_e2, const float* __restrict__ b_e2)
{
    int rl = threadIdx.x >> 6;
    int j  = threadIdx.x & 63;
    size_t r = (size_t)blockIdx.x * 4 + rl;

    __shared__ float pt[4][44];
    __shared__ float m [4][2][64];

    if (j < 44) pt[rl][j] = coords[r*88 + ((j>>1)<<2) + (j&1)];
    __syncthreads();

    float w0 = W_e1[j], w1 = W_e1[64+j], bb = b_e1[j];
    float s1 = 0.f, s2 = 0.f;
#pragma unroll
    for (int p = 0; p < 11; p++){
        float hh = fmaf(pt[rl][2*p+1], w1, fmaf(pt[rl][2*p], w0, bb));
        s1 += fmaxf(hh, 0.f);
    }
#pragma unroll
    for (int p = 11; p < 22; p++){
        float hh = fmaf(pt[rl][2*p+1], w1, fmaf(pt[rl][2*p], w0, bb));
        s2 += fmaxf(hh, 0.f);
    }
    m[rl][0][j] = s1 * (1.0f/11.0f);
    m[rl][1][j] = s2 * (1.0f/11.0f);
    __syncthreads();

    float o1 = b_e2[j], o2 = b_e2[j];
#pragma unroll
    for (int k = 0; k < 64; k++){
        float w = W_e2[k*64 + j];
        o1 = fmaf(m[rl][0][k], w, o1);
        o2 = fmaf(m[rl][1][k], w, o2);
    }
    g_enc[r*128 + j]      = o1;
    g_enc[r*128 + 64 + j] = o2;
}

/* ================= Kernel 2: Xpre GEMM =================
   Output layout: g_xpre[r][h8*128 + u_local*4 + g], u_local 0..31,
   gate order g = i,f,g,o. Consumer CTA h8 reads one contiguous 128-
   float block per row, with all 4 gates of a unit adjacent.           */
__global__ void __launch_bounds__(256) xpre_kernel(
    const float* __restrict__ coords, const float* __restrict__ W_ih,
    const float* __restrict__ b_ih,   const float* __restrict__ b_hh)
{
    extern __shared__ float smx[];
    float* a_s = smx;            /* 32*132 = 4224 */
    float* w_s = a_s + 4224;     /* 32*64  = 2048 */
    float* epi = w_s + 2048;     /* 128*65 = 8320 */

    int h  = blockIdx.x;                 /* h16: 16 tiles of 16 units */
    size_t m0 = (size_t)blockIdx.y * 128;
    int tid = threadIdx.x;
    int tb = tid & 31, tu = tid >> 5;

    u64 acc2[4][4];
#pragma unroll
    for (int bi=0;bi<4;bi++)
#pragma unroll
        for (int g=0;g<4;g++) acc2[bi][g] = 0ULL;

    for (int k0 = 0; k0 < 172; k0 += 32){
#pragma unroll
        for (int i = 0; i < 16; i++){
            int li  = tid + i*256;
            int kk  = li & 31, row = li >> 5;
            int k   = k0 + kk;
            float v = 0.f;
            size_t r = m0 + row;
            if (k < 44)       v = coords[r*88 + ((k>>1)<<2) + (k&1)];
            else if (k < 172) v = g_enc[r*128 + (k-44)];
            a_s[kk*132 + row] = v;
        }
#pragma unroll
        for (int i = 0; i < 8; i++){
            int li = tid + i*256;
            int c  = li & 63, kk = li >> 6;
            int k  = k0 + kk;
            float v = 0.f;
            if (k < 172){
                int col = ((c>>4)<<8) + (h<<4) + (c&15);
                v = W_ih[k*1024 + col];
            }
            w_s[kk*64 + c] = v;
        }
        __syncthreads();
#pragma unroll
        for (int kk = 0; kk < 32; kk++){
            float4 a = *(const float4*)&a_s[kk*132 + 4*tb];
            u64 ax = pack2(a.x,a.x), ay = pack2(a.y,a.y);
            u64 az = pack2(a.z,a.z), aw = pack2(a.w,a.w);
            int kw = kk*64 + (tu<<1);
#pragma unroll
            for (int g = 0; g < 4; g++){
                u64 w2 = *(const u64*)&w_s[kw + g*16];
                acc2[0][g] = fma2(ax, w2, acc2[0][g]);
                acc2[1][g] = fma2(ay, w2, acc2[1][g]);
                acc2[2][g] = fma2(az, w2, acc2[2][g]);
                acc2[3][g] = fma2(aw, w2, acc2[3][g]);
            }
        }
        __syncthreads();
    }

#pragma unroll
    for (int g = 0; g < 4; g++){
        int col0 = (g<<8) + (h<<4) + 2*tu;
        float b0 = b_ih[col0]   + b_hh[col0];
        float b1 = b_ih[col0+1] + b_hh[col0+1];
#pragma unroll
        for (int bi = 0; bi < 4; bi++){
            float lo, hi; unpack2(acc2[bi][g], lo, hi);
            epi[(4*tb+bi)*65 + g*16 + 2*tu]     = lo + b0;
            epi[(4*tb+bi)*65 + g*16 + 2*tu + 1] = hi + b1;
        }
    }
    __syncthreads();
    /* store: for unit j (0..15 in this h16 tile), gates 0..3 contiguous */
#pragma unroll
    for (int i = 0; i < 8; i++){
        int li = tid + i*256;            /* 2048 = 128 rows x 16 units */
        int row = li >> 4, j = li & 15;
        size_t r = m0 + row;
        int colp = (h>>1)*128 + ((h&1)*16 + j)*4;
        float4 v = make_float4(epi[row*65 +      j], epi[row*65 + 16 + j],
                               epi[row*65 + 32 + j], epi[row*65 + 48 + j]);
        *(float4*)&g_xpre[r*1024 + colp] = v;
    }
}

/* ================= Kernel 3: persistent cluster recurrence =================
   grid (8,16): 16 independent 8-CTA clusters, one per 64-row batch tile.
   CTA (h, bm): 64 rows x 32 units x 4 gates. Thread: 8 rows x 1 unit x 4
   gates (GEMM and pointwise share the map -> accs stay in registers).
   W_hh in SMEM [k][u*4+g]; hx staged duplicated (v,v) so fma2 needs no
   packing; cx in regs; one release fence + cluster barrier per step.       */
#define RNN_SMEM_FLOATS (32768 + 8448 + 4224 + 2304 + 64 + 64 + 64 + 64)

__global__ void __launch_bounds__(256,1) __cluster_dims__(8,1,1)
rnn_all_kernel(const float* __restrict__ coords, const float* __restrict__ W_ih,
               const float* __restrict__ W_hh,   const float* __restrict__ W_out,
               const float* __restrict__ b_out,  const float* __restrict__ pitch)
{
    extern __shared__ float sm[];
    float* w_s    = sm;                    /* [256][128] c=u*4+g : 32768 */
    float* xpre_s = w_s    + 32768;        /* [64][132]          :  8448 */
    u64*   hx_d   = (u64*)(xpre_s + 8448); /* [32][66] u64 dup   :  4224f */
    float* epi    = (float*)(hx_d + 2112); /* [64][36]           :  2304 */
    float* wo_s   = epi    + 2304;         /* [32][2]            :    64 */
    float* clo_s  = wo_s   + 64;
    float* px_s   = clo_s  + 64;
    float* py_s   = px_s   + 64;

    int h = blockIdx.x, bm = blockIdx.y;
    int tid = threadIdx.x;
    int u  = tid >> 3;                     /* unit 0..31  */
    int rb = tid & 7;                      /* row block   */

    /* ---- one-time: W_hh slice -> smem [k][u*4+g] (coalesced gather) ---- */
#pragma unroll
    for (int i = 0; i < 32; i++){
        int li = tid + i*256;              /* 8192 f4 = 256 k x 32 c4 */
        int k = li >> 5, c4 = li & 31;
        int g = c4 >> 3, u0 = (c4 & 7) * 4;
        float4 v = *(const float4*)&W_hh[k*1024 + g*256 + h*32 + u0];
        w_s[k*128 + (u0+0)*4 + g] = v.x;
        w_s[k*128 + (u0+1)*4 + g] = v.y;
        w_s[k*128 + (u0+2)*4 + g] = v.z;
        w_s[k*128 + (u0+3)*4 + g] = v.w;
    }
    if (tid < 64){
        int uu = tid >> 1, d = tid & 1;
        wo_s[tid] = W_out[((size_t)(h*32+uu))*90 + 88 + d];
    }
    /* critical-path W_ih rows (closest, pred_x, pred_y) in regs */
    float cw[3][4];
#pragma unroll
    for (int j = 0; j < 3; j++)
#pragma unroll
        for (int g = 0; g < 4; g++)
            cw[j][g] = W_ih[(172+j)*1024 + g*256 + h*32 + u];

    float ps0 = pitch[0], ps1 = pitch[1];
    float bo88 = b_out[88], bo89 = b_out[89];

    float cx[8];
#pragma unroll
    for (int r = 0; r < 8; r++) cx[r] = 0.f;

    __syncthreads();

    int prow = tid >> 3, pc4 = (tid & 7) << 2;   /* hx staging mapping */

    for (int t = 0; t < NSEQ; t++){
        /* ---- pred + closest distance (per batch row) ---- */
        if (tid < 64){
            int bg = bm*64 + tid;
            float px = 0.f, py = 0.f;
            if (t > 0){
                const float* pp = g_predpart[(t-1)&1];
#pragma unroll
                for (int hh = 0; hh < 8; hh++){
                    float2 v = __ldcg((const float2*)&pp[((size_t)hh*NBATCH + bg)*2]);
                    px += v.x; py += v.y;
                }
                px = (px + bo88) * ps0;
                py = (py + bo89) * ps1;
            }
            const float* cp = coords + ((size_t)bg*NSEQ + t)*88;
            float md = 3.402823e38f;
#pragma unroll
            for (int p = 0; p < 22; p++){
                float dx = px - __ldg(&cp[4*p]), dy = py - __ldg(&cp[4*p+1]);
                md = fminf(md, fmaf(dx,dx,dy*dy));
            }
            clo_s[tid] = sqrtf(md);
            px_s[tid] = px; py_s[tid] = py;
        }
        /* ---- xpre tile -> smem (coalesced) ---- */
#pragma unroll
        for (int i = 0; i < 8; i++){
            int li = tid + i*256;          /* 2048 f4 = 64 rows x 32 c4 */
            int row = li >> 5, c4 = li & 31;
            size_t r = ((size_t)(bm*64 + row))*NSEQ + t;
            float4 v = __ldcg((const float4*)&g_xpre[r*1024 + h*128 + 4*c4]);
            *(float4*)&xpre_s[row*132 + 4*c4] = v;
        }

        u64 acc2[8][2];
#pragma unroll
        for (int r = 0; r < 8; r++){ acc2[r][0] = 0ULL; acc2[r][1] = 0ULL; }

        if (t > 0){
            const float* hx = g_hseq + ((size_t)(t-1)*NBATCH + bm*64)*256;
            float4 pf0 = __ldcg((const float4*)&hx[prow*256 + pc4]);
            float4 pf1 = __ldcg((const float4*)&hx[(prow+32)*256 + pc4]);
            for (int kc = 0; kc < 8; kc++){
                __syncthreads();
                hx_d[(pc4+0)*66 + prow] = pack2(pf0.x, pf0.x);
                hx_d[(pc4+1)*66 + prow] = pack2(pf0.y, pf0.y);
                hx_d[(pc4+2)*66 + prow] = pack2(pf0.z, pf0.z);
                hx_d[(pc4+3)*66 + prow] = pack2(pf0.w, pf0.w);
                hx_d[(pc4+0)*66 + prow+32] = pack2(pf1.x, pf1.x);
                hx_d[(pc4+1)*66 + prow+32] = pack2(pf1.y, pf1.y);
                hx_d[(pc4+2)*66 + prow+32] = pack2(pf1.z, pf1.z);
                hx_d[(pc4+3)*66 + prow+32] = pack2(pf1.w, pf1.w);
                __syncthreads();
                int kcn = (kc < 7) ? kc+1 : 7;
                pf0 = __ldcg((const float4*)&hx[prow*256 + kcn*32 + pc4]);
                pf1 = __ldcg((const float4*)&hx[(prow+32)*256 + kcn*32 + pc4]);
#pragma unroll
                for (int kk = 0; kk < 32; kk++){
                    const u64* ak = hx_d + kk*66 + rb*8;
                    const float* wk = w_s + (kc*32 + kk)*128 + u*4;
                    u64 w01 = *(const u64*)wk;
                    u64 w23 = *(const u64*)(wk + 2);
#pragma unroll
                    for (int r = 0; r < 8; r++){
                        u64 a = ak[r];
                        acc2[r][0] = fma2(a, w01, acc2[r][0]);
                        acc2[r][1] = fma2(a, w23, acc2[r][1]);
                    }
                }
            }
        }
        __syncthreads();

        /* ---- LSTM pointwise: regs all the way ---- */
#pragma unroll
        for (int r = 0; r < 8; r++){
            int row = rb*8 + r;
            float4 xv = *(const float4*)&xpre_s[row*132 + u*4];
            float clo = clo_s[row], ppx = px_s[row], ppy = py_s[row];
            float gi, gf, gg, go;
            unpack2(acc2[r][0], gi, gf);
            unpack2(acc2[r][1], gg, go);
            gi += xv.x + clo*cw[0][0] + ppx*cw[1][0] + ppy*cw[2][0];
            gf += xv.y + clo*cw[0][1] + ppx*cw[1][1] + ppy*cw[2][1];
            gg += xv.z + clo*cw[0][2] + ppx*cw[1][2] + ppy*cw[2][2];
            go += xv.w + clo*cw[0][3] + ppx*cw[1][3] + ppy*cw[2][3];
            float c2 = sigmoidf_(gf)*cx[r] + sigmoidf_(gi)*tanhf(gg);
            float h2 = sigmoidf_(go)*tanhf(c2);
            cx[r] = c2;
            epi[row*36 + u] = h2;
        }
        __syncthreads();

        /* ---- hseq store (coalesced) ---- */
        {
            float* hout = g_hseq + ((size_t)t*NBATCH + bm*64)*256 + h*32;
#pragma unroll
            for (int i = 0; i < 2; i++){
                int li = tid + i*256;      /* 512 f4 = 64 rows x 8 f4 */
                int row = li >> 3, c4 = li & 7;
                float4 v = make_float4(epi[row*36 + 4*c4],   epi[row*36 + 4*c4+1],
                                       epi[row*36 + 4*c4+2], epi[row*36 + 4*c4+3]);
                *(float4*)&hout[row*256 + 4*c4] = v;
            }
        }
        /* ---- pred partials for step t+1 ---- */
        if (tid < 64){
            int bg = bm*64 + tid;
            float px = 0.f, py = 0.f;
#pragma unroll
            for (int uu = 0; uu < 32; uu++){
                float hv = epi[tid*36 + uu];
                px = fmaf(hv, wo_s[2*uu],   px);
                py = fmaf(hv, wo_s[2*uu+1], py);
            }
            *(float2*)&g_predpart[t&1][((size_t)h*NBATCH + bg)*2] = make_float2(px, py);
        }

        /* ---- release fence + cluster barrier ---- */
        __threadfence();
        asm volatile("barrier.cluster.arrive.aligned;" ::: "memory");
        asm volatile("barrier.cluster.wait.aligned;"   ::: "memory");
    }
}

/* ================= Kernel 4: output head GEMM ================= */
__global__ void __launch_bounds__(256) out_kernel(
    const float* __restrict__ W_out, const float* __restrict__ b_out,
    const float* __restrict__ pitch, float* __restrict__ out)
{
    size_t r0 = (size_t)blockIdx.x * 64;
    int tid = threadIdx.x;
    int tx = tid & 15, ty = tid >> 4;

    __shared__ float a_s[32*68];
    __shared__ float w_s[32*96];

    float acc[4][6];
#pragma unroll
    for (int bi=0;bi<4;bi++)
#pragma unroll
        for (int ci=0;ci<6;ci++) acc[bi][ci]=0.f;

    for (int k0 = 0; k0 < 256; k0 += 32){
#pragma unroll
        for (int i = 0; i < 8; i++){
            int li = tid + i*256;
            int kk = li & 31, row = li >> 5;
            size_t r = r0 + row;
            int t = (int)(r % NSEQ), b = (int)(r / NSEQ);
            a_s[kk*68 + row] = g_hseq[((size_t)t*NBATCH + b)*256 + k0 + kk];
        }
#pragma unroll
        for (int i = 0; i < 12; i++){
            int li = tid + i*256;
            int n = li % 96, kk = li / 96;
            w_s[kk*96 + n] = (n < 90) ? W_out[(k0+kk)*90 + n] : 0.f;
        }
        __syncthreads();
#pragma unroll
        for (int kk = 0; kk < 32; kk++){
            float4 a = *(const float4*)&a_s[kk*68 + 4*ty];
            float w[6];
#pragma unroll
            for (int ci = 0; ci < 6; ci++) w[ci] = w_s[kk*96 + 6*tx + ci];
#pragma unroll
            for (int ci = 0; ci < 6; ci++){
                acc[0][ci] = fmaf(a.x, w[ci], acc[0][ci]);
                acc[1][ci] = fmaf(a.y, w[ci], acc[1][ci]);
                acc[2][ci] = fmaf(a.z, w[ci], acc[2][ci]);
                acc[3][ci] = fmaf(a.w, w[ci], acc[3][ci]);
            }
        }
        __syncthreads();
    }
#pragma unroll
    for (int bi = 0; bi < 4; bi++){
        size_t r = r0 + 4*ty + bi;
#pragma unroll
        for (int ci = 0; ci < 6; ci++){
            int n = 6*tx + ci;
            if (n < 90)
                out[r*90 + n] = (acc[bi][ci] + b_out[n]) * pitch[n & 1];
        }
    }
}

/* ================= host launcher ================= */
extern "C" void kernel_launch(void* const* d_in, const int* in_sizes, int n_in,
                              void* d_out, int out_size)
{
    const float* coords = (const float*)d_in[0];
    const float* pitch  = (const float*)d_in[1];
    const float* W_e1   = (const float*)d_in[2];
    const float* b_e1   = (const float*)d_in[3];
    const float* W_e2   = (const float*)d_in[4];
    const float* b_e2   = (const float*)d_in[5];
    const float* W_ih   = (const float*)d_in[6];
    const float* b_ih   = (const float*)d_in[7];
    const float* W_hh   = (const float*)d_in[8];
    const float* b_hh   = (const float*)d_in[9];
    const float* W_out  = (const float*)d_in[10];
    const float* b_out  = (const float*)d_in[11];
    float* out = (float*)d_out;

    size_t xpre_smem = 14592u * sizeof(float);                  /*  58,368 B */
    size_t rnn_smem  = (size_t)RNN_SMEM_FLOATS * sizeof(float); /* 192,000 B */
    static int attr_done = 0;
    if (!attr_done){
        cudaFuncSetAttribute(xpre_kernel, cudaFuncAttributeMaxDynamicSharedMemorySize,
                             (int)xpre_smem);
        cudaFuncSetAttribute(rnn_all_kernel, cudaFuncAttributeMaxDynamicSharedMemorySize,
                             (int)rnn_smem);
        attr_done = 1;
    }

    enc_kernel<<<NROWS/4, 256>>>(coords, W_e1, b_e1, W_e2, b_e2);
    xpre_kernel<<<dim3(16, NROWS/128), 256, xpre_smem>>>(coords, W_ih, b_ih, b_hh);
    rnn_all_kernel<<<dim3(8,16), 256, rnn_smem>>>(coords, W_ih, W_hh, W_out, b_out, pitch);
    out_kernel<<<NROWS/64, 256>>>(W_out, b_out, pitch, out);
}

// round 7
// speedup vs baseline: 2.9906x; 2.9906x over previous
#include <cuda_runtime.h>
#include <math.h>

#define NBATCH 1024
#define NSEQ   200
#define NROWS  (NBATCH*NSEQ)   /* 204800 */
#define HXS    92              /* hx_s stride per kk (8 groups of 8 rows + 4 pad) */

/* ------------ static scratch (no allocations allowed) ------------ */
__device__ float g_enc [NROWS*128];           /* encoder output                    */
__device__ float g_xpre[NROWS*1024];          /* gate preacts, [r][h8*128 + u*4+g] */
__device__ float g_hseq[NSEQ*NBATCH*256];     /* hx per step (output GEMM input)   */
__device__ float g_hseqT[2][256*NBATCH];      /* transposed hx, parity-buffered    */
__device__ float g_predpart[2][8*NBATCH*2];   /* parity-buffered pred partials     */

typedef unsigned long long u64;

__device__ __forceinline__ u64 pack2(float lo, float hi){
    u64 r; asm("mov.b64 %0,{%1,%2};" : "=l"(r) : "f"(lo), "f"(hi)); return r;
}
__device__ __forceinline__ void unpack2(u64 v, float& lo, float& hi){
    asm("mov.b64 {%0,%1},%2;" : "=f"(lo), "=f"(hi) : "l"(v));
}
__device__ __forceinline__ u64 fma2(u64 a, u64 b, u64 c){
    u64 d; asm("fma.rn.f32x2 %0,%1,%2,%3;" : "=l"(d) : "l"(a), "l"(b), "l"(c)); return d;
}
__device__ __forceinline__ float sigmoidf_(float x){
    return __fdividef(1.0f, 1.0f + __expf(-x));
}

/* ================= Kernel 1: per-(b,t) set encoder ================= */
__global__ void enc_kernel(const float* __restrict__ coords,
                           const float* __restrict__ W_e1, const float* __restrict__ b_e1,
                           const float* __restrict__ W_e2, const float* __restrict__ b_e2)
{
    int rl = threadIdx.x >> 6;
    int j  = threadIdx.x & 63;
    size_t r = (size_t)blockIdx.x * 4 + rl;

    __shared__ float pt[4][44];
    __shared__ float m [4][2][64];

    if (j < 44) pt[rl][j] = coords[r*88 + ((j>>1)<<2) + (j&1)];
    __syncthreads();

    float w0 = W_e1[j], w1 = W_e1[64+j], bb = b_e1[j];
    float s1 = 0.f, s2 = 0.f;
#pragma unroll
    for (int p = 0; p < 11; p++){
        float hh = fmaf(pt[rl][2*p+1], w1, fmaf(pt[rl][2*p], w0, bb));
        s1 += fmaxf(hh, 0.f);
    }
#pragma unroll
    for (int p = 11; p < 22; p++){
        float hh = fmaf(pt[rl][2*p+1], w1, fmaf(pt[rl][2*p], w0, bb));
        s2 += fmaxf(hh, 0.f);
    }
    m[rl][0][j] = s1 * (1.0f/11.0f);
    m[rl][1][j] = s2 * (1.0f/11.0f);
    __syncthreads();

    float o1 = b_e2[j], o2 = b_e2[j];
#pragma unroll
    for (int k = 0; k < 64; k++){
        float w = W_e2[k*64 + j];
        o1 = fmaf(m[rl][0][k], w, o1);
        o2 = fmaf(m[rl][1][k], w, o2);
    }
    g_enc[r*128 + j]      = o1;
    g_enc[r*128 + 64 + j] = o2;
}

/* ================= Kernel 2: Xpre GEMM =================
   Output layout: g_xpre[r][h8*128 + u_local*4 + g], u_local 0..31.    */
__global__ void __launch_bounds__(256) xpre_kernel(
    const float* __restrict__ coords, const float* __restrict__ W_ih,
    const float* __restrict__ b_ih,   const float* __restrict__ b_hh)
{
    extern __shared__ float smx[];
    float* a_s = smx;            /* 32*132 = 4224 */
    float* w_s = a_s + 4224;     /* 32*64  = 2048 */
    float* epi = w_s + 2048;     /* 128*65 = 8320 */

    int h  = blockIdx.x;                 /* h16: 16 tiles of 16 units */
    size_t m0 = (size_t)blockIdx.y * 128;
    int tid = threadIdx.x;
    int tb = tid & 31, tu = tid >> 5;

    u64 acc2[4][4];
#pragma unroll
    for (int bi=0;bi<4;bi++)
#pragma unroll
        for (int g=0;g<4;g++) acc2[bi][g] = 0ULL;

    for (int k0 = 0; k0 < 172; k0 += 32){
#pragma unroll
        for (int i = 0; i < 16; i++){
            int li  = tid + i*256;
            int kk  = li & 31, row = li >> 5;
            int k   = k0 + kk;
            float v = 0.f;
            size_t r = m0 + row;
            if (k < 44)       v = coords[r*88 + ((k>>1)<<2) + (k&1)];
            else if (k < 172) v = g_enc[r*128 + (k-44)];
            a_s[kk*132 + row] = v;
        }
#pragma unroll
        for (int i = 0; i < 8; i++){
            int li = tid + i*256;
            int c  = li & 63, kk = li >> 6;
            int k  = k0 + kk;
            float v = 0.f;
            if (k < 172){
                int col = ((c>>4)<<8) + (h<<4) + (c&15);
                v = W_ih[k*1024 + col];
            }
            w_s[kk*64 + c] = v;
        }
        __syncthreads();
#pragma unroll
        for (int kk = 0; kk < 32; kk++){
            float4 a = *(const float4*)&a_s[kk*132 + 4*tb];
            u64 ax = pack2(a.x,a.x), ay = pack2(a.y,a.y);
            u64 az = pack2(a.z,a.z), aw = pack2(a.w,a.w);
            int kw = kk*64 + (tu<<1);
#pragma unroll
            for (int g = 0; g < 4; g++){
                u64 w2 = *(const u64*)&w_s[kw + g*16];
                acc2[0][g] = fma2(ax, w2, acc2[0][g]);
                acc2[1][g] = fma2(ay, w2, acc2[1][g]);
                acc2[2][g] = fma2(az, w2, acc2[2][g]);
                acc2[3][g] = fma2(aw, w2, acc2[3][g]);
            }
        }
        __syncthreads();
    }

#pragma unroll
    for (int g = 0; g < 4; g++){
        int col0 = (g<<8) + (h<<4) + 2*tu;
        float b0 = b_ih[col0]   + b_hh[col0];
        float b1 = b_ih[col0+1] + b_hh[col0+1];
#pragma unroll
        for (int bi = 0; bi < 4; bi++){
            float lo, hi; unpack2(acc2[bi][g], lo, hi);
            epi[(4*tb+bi)*65 + g*16 + 2*tu]     = lo + b0;
            epi[(4*tb+bi)*65 + g*16 + 2*tu + 1] = hi + b1;
        }
    }
    __syncthreads();
#pragma unroll
    for (int i = 0; i < 8; i++){
        int li = tid + i*256;            /* 2048 = 128 rows x 16 units */
        int row = li >> 4, j = li & 15;
        size_t r = m0 + row;
        int colp = (h>>1)*128 + ((h&1)*16 + j)*4;
        float4 v = make_float4(epi[row*65 +      j], epi[row*65 + 16 + j],
                               epi[row*65 + 32 + j], epi[row*65 + 48 + j]);
        *(float4*)&g_xpre[r*1024 + colp] = v;
    }
}

/* ================= Kernel 3: persistent cluster recurrence =================
   grid (8,16): 16 independent 8-CTA clusters (batch tiles of 64 rows).
   CTA (h, bm): 64 rows x 32 units x 4 gates. Thread: 8 rows x 1 unit.
   Row-pair-packed f32x2 GEMM: per kk 2 LDS.128 (a) + 1 LDS.128 (w) +
   4 dup movs + 16 fma2 -> fma-pipe bound, all LDS conflict-free.
   hx staged ONCE per step from transposed double buffer g_hseqT.          */
#define RNN_SMEM_FLOATS (32768 + 256*HXS + 64 + 64 + 64 + 64)

__global__ void __launch_bounds__(256,1) __cluster_dims__(8,1,1)
rnn_all_kernel(const float* __restrict__ coords, const float* __restrict__ W_ih,
               const float* __restrict__ W_hh,   const float* __restrict__ W_out,
               const float* __restrict__ b_out,  const float* __restrict__ pitch)
{
    extern __shared__ float sm[];
    float* w_s   = sm;                     /* [256][128] c=u*4+g : 32768 f */
    float* hx_s  = w_s + 32768;            /* [256][HXS]         : 23552 f */
    float* epi   = hx_s;                   /* overlay, [row*33+u]: 2112 f  */
    float* wo_s  = hx_s + 256*HXS;         /* [32][2] */
    float* clo_s = wo_s + 64;
    float* px_s  = clo_s + 64;
    float* py_s  = px_s + 64;

    int h = blockIdx.x, bm = blockIdx.y;
    int tid = threadIdx.x;
    int u  = tid >> 3;                     /* unit 0..31 */
    int rb = tid & 7;                      /* row-block  */

    /* ---- one-time: W_hh slice -> smem [k][u*4+g] ---- */
#pragma unroll
    for (int i = 0; i < 32; i++){
        int li = tid + i*256;              /* 8192 f4 = 256 k x 32 c4 */
        int k = li >> 5, c4 = li & 31;
        int g = c4 >> 3, u0 = (c4 & 7) * 4;
        float4 v = *(const float4*)&W_hh[k*1024 + g*256 + h*32 + u0];
        w_s[k*128 + (u0+0)*4 + g] = v.x;
        w_s[k*128 + (u0+1)*4 + g] = v.y;
        w_s[k*128 + (u0+2)*4 + g] = v.z;
        w_s[k*128 + (u0+3)*4 + g] = v.w;
    }
    if (tid < 64){
        int uu = tid >> 1, d = tid & 1;
        wo_s[tid] = W_out[((size_t)(h*32+uu))*90 + 88 + d];
    }
    float cw[3][4];
#pragma unroll
    for (int j = 0; j < 3; j++)
#pragma unroll
        for (int g = 0; g < 4; g++)
            cw[j][g] = W_ih[(172+j)*1024 + g*256 + h*32 + u];

    float ps0 = pitch[0], ps1 = pitch[1];
    float bo88 = b_out[88], bo89 = b_out[89];

    float cx[8];
#pragma unroll
    for (int r = 0; r < 8; r++) cx[r] = 0.f;

    __syncthreads();

    for (int t = 0; t < NSEQ; t++){
        /* ---- pred + closest distance (per batch row) ---- */
        if (tid < 64){
            int bg = bm*64 + tid;
            float px = 0.f, py = 0.f;
            if (t > 0){
                const float* pp = g_predpart[(t-1)&1];
#pragma unroll
                for (int hh = 0; hh < 8; hh++){
                    float2 v = __ldcg((const float2*)&pp[((size_t)hh*NBATCH + bg)*2]);
                    px += v.x; py += v.y;
                }
                px = (px + bo88) * ps0;
                py = (py + bo89) * ps1;
            }
            const float* cp = coords + ((size_t)bg*NSEQ + t)*88;
            float md = 3.402823e38f;
#pragma unroll
            for (int p = 0; p < 22; p++){
                float dx = px - __ldg(&cp[4*p]), dy = py - __ldg(&cp[4*p+1]);
                md = fminf(md, fmaf(dx,dx,dy*dy));
            }
            clo_s[tid] = sqrtf(md);
            px_s[tid] = px; py_s[tid] = py;
        }

        u64 acc[4][4];
#pragma unroll
        for (int rp=0;rp<4;rp++)
#pragma unroll
            for (int g=0;g<4;g++) acc[rp][g] = 0ULL;

        if (t > 0){
            /* ---- stage hx (all K) from transposed buffer, coalesced ---- */
            const float* hT = g_hseqT[(t-1)&1] + bm*64;
#pragma unroll
            for (int i = 0; i < 32; i++){
                int li = tid + i*256;      /* 8192 f2 = 256 k x 32 pairs */
                int k = li >> 5, l = li & 31;
                float2 v = __ldcg((const float2*)&hT[k*1024 + 2*l]);
                int rp = 2*l + (l>>2)*4;   /* group stride 12: rp = 12q+2s */
                *(float2*)&hx_s[k*HXS + rp] = v;
            }
            __syncthreads();

            /* ---- GEMM: 256 kk, fma2 row-pair packed ---- */
            const float* hbase = hx_s + rb*12;   /* FIX: group stride is 12 */
            const float* wbase = w_s + u*4;
#pragma unroll 8
            for (int kk = 0; kk < 256; kk++){
                ulonglong2 A01 = *(const ulonglong2*)(hbase + kk*HXS);
                ulonglong2 A23 = *(const ulonglong2*)(hbase + kk*HXS + 4);
                float4 wv = *(const float4*)(wbase + kk*128);
                u64 w0 = pack2(wv.x, wv.x), w1 = pack2(wv.y, wv.y);
                u64 w2 = pack2(wv.z, wv.z), w3 = pack2(wv.w, wv.w);
                acc[0][0] = fma2(A01.x, w0, acc[0][0]);
                acc[0][1] = fma2(A01.x, w1, acc[0][1]);
                acc[0][2] = fma2(A01.x, w2, acc[0][2]);
                acc[0][3] = fma2(A01.x, w3, acc[0][3]);
                acc[1][0] = fma2(A01.y, w0, acc[1][0]);
                acc[1][1] = fma2(A01.y, w1, acc[1][1]);
                acc[1][2] = fma2(A01.y, w2, acc[1][2]);
                acc[1][3] = fma2(A01.y, w3, acc[1][3]);
                acc[2][0] = fma2(A23.x, w0, acc[2][0]);
                acc[2][1] = fma2(A23.x, w1, acc[2][1]);
                acc[2][2] = fma2(A23.x, w2, acc[2][2]);
                acc[2][3] = fma2(A23.x, w3, acc[2][3]);
                acc[3][0] = fma2(A23.y, w0, acc[3][0]);
                acc[3][1] = fma2(A23.y, w1, acc[3][1]);
                acc[3][2] = fma2(A23.y, w2, acc[3][2]);
                acc[3][3] = fma2(A23.y, w3, acc[3][3]);
            }
        }
        __syncthreads();   /* hx_s reads done -> epi overlay is safe */

        /* ---- LSTM pointwise (xpre direct from global) ---- */
#pragma unroll
        for (int r = 0; r < 8; r++){
            int row = rb*8 + r;
            size_t rglob = ((size_t)(bm*64 + row))*NSEQ + t;
            float4 xv = __ldcg((const float4*)&g_xpre[rglob*1024 + h*128 + u*4]);
            float clo = clo_s[row], ppx = px_s[row], ppy = py_s[row];
            float lo0, hi0, lo1, hi1, lo2, hi2, lo3, hi3;
            unpack2(acc[r>>1][0], lo0, hi0);
            unpack2(acc[r>>1][1], lo1, hi1);
            unpack2(acc[r>>1][2], lo2, hi2);
            unpack2(acc[r>>1][3], lo3, hi3);
            float gi = (r&1) ? hi0 : lo0;
            float gf = (r&1) ? hi1 : lo1;
            float gg = (r&1) ? hi2 : lo2;
            float go = (r&1) ? hi3 : lo3;
            gi += xv.x + clo*cw[0][0] + ppx*cw[1][0] + ppy*cw[2][0];
            gf += xv.y + clo*cw[0][1] + ppx*cw[1][1] + ppy*cw[2][1];
            gg += xv.z + clo*cw[0][2] + ppx*cw[1][2] + ppy*cw[2][2];
            go += xv.w + clo*cw[0][3] + ppx*cw[1][3] + ppy*cw[2][3];
            float c2 = sigmoidf_(gf)*cx[r] + sigmoidf_(gi)*tanhf(gg);
            float h2 = sigmoidf_(go)*tanhf(c2);
            cx[r] = c2;
            epi[row*33 + u] = h2;
        }
        __syncthreads();

        /* ---- plain hseq store [t][b][256] ---- */
        {
            float* hout = g_hseq + ((size_t)t*NBATCH + bm*64)*256 + h*32;
#pragma unroll
            for (int i = 0; i < 8; i++){
                int li = tid + i*256;      /* 2048 = 64 rows x 32 c */
                int row = li >> 5, c = li & 31;
                hout[row*256 + c] = epi[row*33 + c];
            }
        }
        /* ---- transposed hseqT store [t&1][col][1024] ---- */
        {
            float* hT2 = g_hseqT[t&1] + bm*64;
#pragma unroll
            for (int i = 0; i < 8; i++){
                int li = tid + i*256;      /* 2048 = 32 cols x 64 rows */
                int col = li >> 6, row = li & 63;
                hT2[(size_t)(h*32 + col)*1024 + row] = epi[row*33 + col];
            }
        }
        /* ---- pred partials for step t+1 ---- */
        if (tid < 64){
            int bg = bm*64 + tid;
            float px = 0.f, py = 0.f;
#pragma unroll
            for (int uu = 0; uu < 32; uu++){
                float hv = epi[tid*33 + uu];
                px = fmaf(hv, wo_s[2*uu],   px);
                py = fmaf(hv, wo_s[2*uu+1], py);
            }
            *(float2*)&g_predpart[t&1][((size_t)h*NBATCH + bg)*2] = make_float2(px, py);
        }

        /* ---- release fence + cluster barrier ---- */
        __threadfence();
        asm volatile("barrier.cluster.arrive.aligned;" ::: "memory");
        asm volatile("barrier.cluster.wait.aligned;"   ::: "memory");
    }
}

/* ================= Kernel 4: output head GEMM ================= */
__global__ void __launch_bounds__(256) out_kernel(
    const float* __restrict__ W_out, const float* __restrict__ b_out,
    const float* __restrict__ pitch, float* __restrict__ out)
{
    size_t r0 = (size_t)blockIdx.x * 64;
    int tid = threadIdx.x;
    int tx = tid & 15, ty = tid >> 4;

    __shared__ float a_s[32*68];
    __shared__ float w_s[32*96];

    float acc[4][6];
#pragma unroll
    for (int bi=0;bi<4;bi++)
#pragma unroll
        for (int ci=0;ci<6;ci++) acc[bi][ci]=0.f;

    for (int k0 = 0; k0 < 256; k0 += 32){
#pragma unroll
        for (int i = 0; i < 8; i++){
            int li = tid + i*256;
            int kk = li & 31, row = li >> 5;
            size_t r = r0 + row;
            int t = (int)(r % NSEQ), b = (int)(r / NSEQ);
            a_s[kk*68 + row] = g_hseq[((size_t)t*NBATCH + b)*256 + k0 + kk];
        }
#pragma unroll
        for (int i = 0; i < 12; i++){
            int li = tid + i*256;
            int n = li % 96, kk = li / 96;
            w_s[kk*96 + n] = (n < 90) ? W_out[(k0+kk)*90 + n] : 0.f;
        }
        __syncthreads();
#pragma unroll
        for (int kk = 0; kk < 32; kk++){
            float4 a = *(const float4*)&a_s[kk*68 + 4*ty];
            float w[6];
#pragma unroll
            for (int ci = 0; ci < 6; ci++) w[ci] = w_s[kk*96 + 6*tx + ci];
#pragma unroll
            for (int ci = 0; ci < 6; ci++){
                acc[0][ci] = fmaf(a.x, w[ci], acc[0][ci]);
                acc[1][ci] = fmaf(a.y, w[ci], acc[1][ci]);
                acc[2][ci] = fmaf(a.z, w[ci], acc[2][ci]);
                acc[3][ci] = fmaf(a.w, w[ci], acc[3][ci]);
            }
        }
        __syncthreads();
    }
#pragma unroll
    for (int bi = 0; bi < 4; bi++){
        size_t r = r0 + 4*ty + bi;
#pragma unroll
        for (int ci = 0; ci < 6; ci++){
            int n = 6*tx + ci;
            if (n < 90)
                out[r*90 + n] = (acc[bi][ci] + b_out[n]) * pitch[n & 1];
        }
    }
}

/* ================= host launcher ================= */
extern "C" void kernel_launch(void* const* d_in, const int* in_sizes, int n_in,
                              void* d_out, int out_size)
{
    const float* coords = (const float*)d_in[0];
    const float* pitch  = (const float*)d_in[1];
    const float* W_e1   = (const float*)d_in[2];
    const float* b_e1   = (const float*)d_in[3];
    const float* W_e2   = (const float*)d_in[4];
    const float* b_e2   = (const float*)d_in[5];
    const float* W_ih   = (const float*)d_in[6];
    const float* b_ih   = (const float*)d_in[7];
    const float* W_hh   = (const float*)d_in[8];
    const float* b_hh   = (const float*)d_in[9];
    const float* W_out  = (const float*)d_in[10];
    const float* b_out  = (const float*)d_in[11];
    float* out = (float*)d_out;

    size_t xpre_smem = 14592u * sizeof(float);                  /*  58,368 B */
    size_t rnn_smem  = (size_t)RNN_SMEM_FLOATS * sizeof(float); /* 95,232+... B */
    static int attr_done = 0;
    if (!attr_done){
        cudaFuncSetAttribute(xpre_kernel, cudaFuncAttributeMaxDynamicSharedMemorySize,
                             (int)xpre_smem);
        cudaFuncSetAttribute(rnn_all_kernel, cudaFuncAttributeMaxDynamicSharedMemorySize,
                             (int)rnn_smem);
        attr_done = 1;
    }

    enc_kernel<<<NROWS/4, 256>>>(coords, W_e1, b_e1, W_e2, b_e2);
    xpre_kernel<<<dim3(16, NROWS/128), 256, xpre_smem>>>(coords, W_ih, b_ih, b_hh);
    rnn_all_kernel<<<dim3(8,16), 256, rnn_smem>>>(coords, W_ih, W_hh, W_out, b_out, pitch);
    out_kernel<<<NROWS/64, 256>>>(W_out, b_out, pitch, out);
}

// round 8
// speedup vs baseline: 3.7634x; 1.2584x over previous
#include <cuda_runtime.h>
#include <math.h>

#define NBATCH 1024
#define NSEQ   200
#define NROWS  (NBATCH*NSEQ)   /* 204800 */
#define HXS    92              /* hx_s stride per kk (8 groups of 8 rows + 4 pad) */

/* ------------ static scratch (no allocations allowed) ------------ */
__device__ float g_enc [NROWS*128];           /* encoder output                    */
__device__ float g_xpre[NROWS*1024];          /* gate preacts, [r][h8*128 + u*4+g] */
__device__ float g_hseq[NSEQ*NBATCH*256];     /* hx per step (output GEMM input)   */
__device__ float g_hseqT[2][256*NBATCH];      /* transposed hx, parity-buffered    */
__device__ float g_cx  [NBATCH*256];          /* cell state, thread-mapped         */
__device__ float g_predpart[2][8*NBATCH*2];   /* parity-buffered pred partials     */

typedef unsigned long long u64;

__device__ __forceinline__ u64 pack2(float lo, float hi){
    u64 r; asm("mov.b64 %0,{%1,%2};" : "=l"(r) : "f"(lo), "f"(hi)); return r;
}
__device__ __forceinline__ void unpack2(u64 v, float& lo, float& hi){
    asm("mov.b64 {%0,%1},%2;" : "=f"(lo), "=f"(hi) : "l"(v));
}
__device__ __forceinline__ u64 fma2(u64 a, u64 b, u64 c){
    u64 d; asm("fma.rn.f32x2 %0,%1,%2,%3;" : "=l"(d) : "l"(a), "l"(b), "l"(c)); return d;
}
__device__ __forceinline__ float sigmoidf_(float x){
    return __fdividef(1.0f, 1.0f + __expf(-x));
}

/* ================= Kernel 1: per-(b,t) set encoder ================= */
__global__ void enc_kernel(const float* __restrict__ coords,
                           const float* __restrict__ W_e1, const float* __restrict__ b_e1,
                           const float* __restrict__ W_e2, const float* __restrict__ b_e2)
{
    int rl = threadIdx.x >> 6;
    int j  = threadIdx.x & 63;
    size_t r = (size_t)blockIdx.x * 4 + rl;

    __shared__ float pt[4][44];
    __shared__ float m [4][2][64];

    if (j < 44) pt[rl][j] = coords[r*88 + ((j>>1)<<2) + (j&1)];
    __syncthreads();

    float w0 = W_e1[j], w1 = W_e1[64+j], bb = b_e1[j];
    float s1 = 0.f, s2 = 0.f;
#pragma unroll
    for (int p = 0; p < 11; p++){
        float hh = fmaf(pt[rl][2*p+1], w1, fmaf(pt[rl][2*p], w0, bb));
        s1 += fmaxf(hh, 0.f);
    }
#pragma unroll
    for (int p = 11; p < 22; p++){
        float hh = fmaf(pt[rl][2*p+1], w1, fmaf(pt[rl][2*p], w0, bb));
        s2 += fmaxf(hh, 0.f);
    }
    m[rl][0][j] = s1 * (1.0f/11.0f);
    m[rl][1][j] = s2 * (1.0f/11.0f);
    __syncthreads();

    float o1 = b_e2[j], o2 = b_e2[j];
#pragma unroll
    for (int k = 0; k < 64; k++){
        float w = W_e2[k*64 + j];
        o1 = fmaf(m[rl][0][k], w, o1);
        o2 = fmaf(m[rl][1][k], w, o2);
    }
    g_enc[r*128 + j]      = o1;
    g_enc[r*128 + 64 + j] = o2;
}

/* ================= Kernel 2: Xpre GEMM =================
   Output layout: g_xpre[r][h8*128 + u_local*4 + g], u_local 0..31.    */
__global__ void __launch_bounds__(256) xpre_kernel(
    const float* __restrict__ coords, const float* __restrict__ W_ih,
    const float* __restrict__ b_ih,   const float* __restrict__ b_hh)
{
    extern __shared__ float smx[];
    float* a_s = smx;            /* 32*132 = 4224 */
    float* w_s = a_s + 4224;     /* 32*64  = 2048 */
    float* epi = w_s + 2048;     /* 128*65 = 8320 */

    int h  = blockIdx.x;                 /* h16: 16 tiles of 16 units */
    size_t m0 = (size_t)blockIdx.y * 128;
    int tid = threadIdx.x;
    int tb = tid & 31, tu = tid >> 5;

    u64 acc2[4][4];
#pragma unroll
    for (int bi=0;bi<4;bi++)
#pragma unroll
        for (int g=0;g<4;g++) acc2[bi][g] = 0ULL;

    for (int k0 = 0; k0 < 172; k0 += 32){
#pragma unroll
        for (int i = 0; i < 16; i++){
            int li  = tid + i*256;
            int kk  = li & 31, row = li >> 5;
            int k   = k0 + kk;
            float v = 0.f;
            size_t r = m0 + row;
            if (k < 44)       v = coords[r*88 + ((k>>1)<<2) + (k&1)];
            else if (k < 172) v = g_enc[r*128 + (k-44)];
            a_s[kk*132 + row] = v;
        }
#pragma unroll
        for (int i = 0; i < 8; i++){
            int li = tid + i*256;
            int c  = li & 63, kk = li >> 6;
            int k  = k0 + kk;
            float v = 0.f;
            if (k < 172){
                int col = ((c>>4)<<8) + (h<<4) + (c&15);
                v = W_ih[k*1024 + col];
            }
            w_s[kk*64 + c] = v;
        }
        __syncthreads();
#pragma unroll
        for (int kk = 0; kk < 32; kk++){
            float4 a = *(const float4*)&a_s[kk*132 + 4*tb];
            u64 ax = pack2(a.x,a.x), ay = pack2(a.y,a.y);
            u64 az = pack2(a.z,a.z), aw = pack2(a.w,a.w);
            int kw = kk*64 + (tu<<1);
#pragma unroll
            for (int g = 0; g < 4; g++){
                u64 w2 = *(const u64*)&w_s[kw + g*16];
                acc2[0][g] = fma2(ax, w2, acc2[0][g]);
                acc2[1][g] = fma2(ay, w2, acc2[1][g]);
                acc2[2][g] = fma2(az, w2, acc2[2][g]);
                acc2[3][g] = fma2(aw, w2, acc2[3][g]);
            }
        }
        __syncthreads();
    }

#pragma unroll
    for (int g = 0; g < 4; g++){
        int col0 = (g<<8) + (h<<4) + 2*tu;
        float b0 = b_ih[col0]   + b_hh[col0];
        float b1 = b_ih[col0+1] + b_hh[col0+1];
#pragma unroll
        for (int bi = 0; bi < 4; bi++){
            float lo, hi; unpack2(acc2[bi][g], lo, hi);
            epi[(4*tb+bi)*65 + g*16 + 2*tu]     = lo + b0;
            epi[(4*tb+bi)*65 + g*16 + 2*tu + 1] = hi + b1;
        }
    }
    __syncthreads();
#pragma unroll
    for (int i = 0; i < 8; i++){
        int li = tid + i*256;            /* 2048 = 128 rows x 16 units */
        int row = li >> 4, j = li & 15;
        size_t r = m0 + row;
        int colp = (h>>1)*128 + ((h&1)*16 + j)*4;
        float4 v = make_float4(epi[row*65 +      j], epi[row*65 + 16 + j],
                               epi[row*65 + 32 + j], epi[row*65 + 48 + j]);
        *(float4*)&g_xpre[r*1024 + colp] = v;
    }
}

/* ================= Kernel 3: one recurrent step =================
   grid (8,16): h = 32-unit tile, bm = 64-row batch tile. 256 threads;
   thread (u=tid>>3, rb=tid&7): 8 rows x 1 unit x 4 gates.
   Per kk: 2 LDS.128 (a, broadcast x4) + 1 LDS.128 (w, broadcast x8)
   + 16 fma2 -> fma2-pipe bound, conflict-free. Kernel boundary = sync. */
#define RNN_SMEM_FLOATS (32768 + 256*HXS + 64 + 64 + 64 + 64)

__global__ void __launch_bounds__(256) rnn_step_kernel(
    const float* __restrict__ coords, const float* __restrict__ W_ih,
    const float* __restrict__ W_hh,   const float* __restrict__ W_out,
    const float* __restrict__ b_out,  const float* __restrict__ pitch, int t)
{
    extern __shared__ float sm[];
    float* w_s   = sm;                     /* [256][128] c=u*4+g : 32768 f */
    float* hx_s  = w_s + 32768;            /* [256][HXS]         : 23552 f */
    float* epi   = hx_s;                   /* overlay, [row*33+u]          */
    float* wo_s  = hx_s + 256*HXS;         /* [32][2] */
    float* clo_s = wo_s + 64;
    float* px_s  = clo_s + 64;
    float* py_s  = px_s + 64;

    int h = blockIdx.x, bm = blockIdx.y;
    int tid = threadIdx.x;
    int u  = tid >> 3;                     /* unit 0..31 */
    int rb = tid & 7;                      /* row-block  */

    /* ---- per-launch: W_hh slice -> smem [k][u*4+g] ---- */
#pragma unroll
    for (int i = 0; i < 32; i++){
        int li = tid + i*256;              /* 8192 f4 = 256 k x 32 c4 */
        int k = li >> 5, c4 = li & 31;
        int g = c4 >> 3, u0 = (c4 & 7) * 4;
        float4 v = *(const float4*)&W_hh[k*1024 + g*256 + h*32 + u0];
        w_s[k*128 + (u0+0)*4 + g] = v.x;
        w_s[k*128 + (u0+1)*4 + g] = v.y;
        w_s[k*128 + (u0+2)*4 + g] = v.z;
        w_s[k*128 + (u0+3)*4 + g] = v.w;
    }
    if (tid < 64){
        int uu = tid >> 1, d = tid & 1;
        wo_s[tid] = W_out[((size_t)(h*32+uu))*90 + 88 + d];
    }
    float cw[3][4];
#pragma unroll
    for (int j = 0; j < 3; j++)
#pragma unroll
        for (int g = 0; g < 4; g++)
            cw[j][g] = W_ih[(172+j)*1024 + g*256 + h*32 + u];

    float ps0 = pitch[0], ps1 = pitch[1];
    float bo88 = b_out[88], bo89 = b_out[89];

    /* ---- pred + closest distance (per batch row) ---- */
    if (tid < 64){
        int bg = bm*64 + tid;
        float px = 0.f, py = 0.f;
        if (t > 0){
            const float* pp = g_predpart[(t-1)&1];
#pragma unroll
            for (int hh = 0; hh < 8; hh++){
                float2 v = __ldcg((const float2*)&pp[((size_t)hh*NBATCH + bg)*2]);
                px += v.x; py += v.y;
            }
            px = (px + bo88) * ps0;
            py = (py + bo89) * ps1;
        }
        const float* cp = coords + ((size_t)bg*NSEQ + t)*88;
        float md = 3.402823e38f;
#pragma unroll
        for (int p = 0; p < 22; p++){
            float dx = px - __ldg(&cp[4*p]), dy = py - __ldg(&cp[4*p+1]);
            md = fminf(md, fmaf(dx,dx,dy*dy));
        }
        clo_s[tid] = sqrtf(md);
        px_s[tid] = px; py_s[tid] = py;
    }

    u64 acc[4][4];
#pragma unroll
    for (int rp=0;rp<4;rp++)
#pragma unroll
        for (int g=0;g<4;g++) acc[rp][g] = 0ULL;

    if (t > 0){
        /* ---- stage hx (all K) from transposed buffer, coalesced ---- */
        const float* hT = g_hseqT[(t-1)&1] + bm*64;
#pragma unroll
        for (int i = 0; i < 32; i++){
            int li = tid + i*256;          /* 8192 f2 = 256 k x 32 pairs */
            int k = li >> 5, l = li & 31;
            float2 v = __ldcg((const float2*)&hT[k*1024 + 2*l]);
            int rp = 2*l + (l>>2)*4;       /* group stride 12: rp = 12q+2s */
            *(float2*)&hx_s[k*HXS + rp] = v;
        }
        __syncthreads();

        /* ---- GEMM: 256 kk, fma2 row-pair packed ---- */
        const float* hbase = hx_s + rb*12;
        const float* wbase = w_s + u*4;
#pragma unroll 4
        for (int kk = 0; kk < 256; kk++){
            ulonglong2 A01 = *(const ulonglong2*)(hbase + kk*HXS);
            ulonglong2 A23 = *(const ulonglong2*)(hbase + kk*HXS + 4);
            float4 wv = *(const float4*)(wbase + kk*128);
            u64 w0 = pack2(wv.x, wv.x), w1 = pack2(wv.y, wv.y);
            u64 w2 = pack2(wv.z, wv.z), w3 = pack2(wv.w, wv.w);
            acc[0][0] = fma2(A01.x, w0, acc[0][0]);
            acc[0][1] = fma2(A01.x, w1, acc[0][1]);
            acc[0][2] = fma2(A01.x, w2, acc[0][2]);
            acc[0][3] = fma2(A01.x, w3, acc[0][3]);
            acc[1][0] = fma2(A01.y, w0, acc[1][0]);
            acc[1][1] = fma2(A01.y, w1, acc[1][1]);
            acc[1][2] = fma2(A01.y, w2, acc[1][2]);
            acc[1][3] = fma2(A01.y, w3, acc[1][3]);
            acc[2][0] = fma2(A23.x, w0, acc[2][0]);
            acc[2][1] = fma2(A23.x, w1, acc[2][1]);
            acc[2][2] = fma2(A23.x, w2, acc[2][2]);
            acc[2][3] = fma2(A23.x, w3, acc[2][3]);
            acc[3][0] = fma2(A23.y, w0, acc[3][0]);
            acc[3][1] = fma2(A23.y, w1, acc[3][1]);
            acc[3][2] = fma2(A23.y, w2, acc[3][2]);
            acc[3][3] = fma2(A23.y, w3, acc[3][3]);
        }
    }
    __syncthreads();   /* hx_s reads done -> epi overlay is safe */

    /* ---- LSTM pointwise; cx streamed via thread-mapped global ---- */
    {
        size_t cxbase = ((size_t)((h*16 + bm)*256 + tid))*8;
        float cx[8];
        if (t > 0){
            float4 c0 = __ldcg((const float4*)&g_cx[cxbase]);
            float4 c1 = __ldcg((const float4*)&g_cx[cxbase+4]);
            cx[0]=c0.x; cx[1]=c0.y; cx[2]=c0.z; cx[3]=c0.w;
            cx[4]=c1.x; cx[5]=c1.y; cx[6]=c1.z; cx[7]=c1.w;
        } else {
#pragma unroll
            for (int r = 0; r < 8; r++) cx[r] = 0.f;
        }
#pragma unroll
        for (int r = 0; r < 8; r++){
            int row = rb*8 + r;
            size_t rglob = ((size_t)(bm*64 + row))*NSEQ + t;
            float4 xv = __ldcg((const float4*)&g_xpre[rglob*1024 + h*128 + u*4]);
            float clo = clo_s[row], ppx = px_s[row], ppy = py_s[row];
            float lo0, hi0, lo1, hi1, lo2, hi2, lo3, hi3;
            unpack2(acc[r>>1][0], lo0, hi0);
            unpack2(acc[r>>1][1], lo1, hi1);
            unpack2(acc[r>>1][2], lo2, hi2);
            unpack2(acc[r>>1][3], lo3, hi3);
            float gi = (r&1) ? hi0 : lo0;
            float gf = (r&1) ? hi1 : lo1;
            float gg = (r&1) ? hi2 : lo2;
            float go = (r&1) ? hi3 : lo3;
            gi += xv.x + clo*cw[0][0] + ppx*cw[1][0] + ppy*cw[2][0];
            gf += xv.y + clo*cw[0][1] + ppx*cw[1][1] + ppy*cw[2][1];
            gg += xv.z + clo*cw[0][2] + ppx*cw[1][2] + ppy*cw[2][2];
            go += xv.w + clo*cw[0][3] + ppx*cw[1][3] + ppy*cw[2][3];
            float c2 = sigmoidf_(gf)*cx[r] + sigmoidf_(gi)*tanhf(gg);
            float h2 = sigmoidf_(go)*tanhf(c2);
            cx[r] = c2;
            epi[row*33 + u] = h2;
        }
        *(float4*)&g_cx[cxbase]   = make_float4(cx[0],cx[1],cx[2],cx[3]);
        *(float4*)&g_cx[cxbase+4] = make_float4(cx[4],cx[5],cx[6],cx[7]);
    }
    __syncthreads();

    /* ---- plain hseq store [t][b][256] ---- */
    {
        float* hout = g_hseq + ((size_t)t*NBATCH + bm*64)*256 + h*32;
#pragma unroll
        for (int i = 0; i < 8; i++){
            int li = tid + i*256;          /* 2048 = 64 rows x 32 c */
            int row = li >> 5, c = li & 31;
            hout[row*256 + c] = epi[row*33 + c];
        }
    }
    /* ---- transposed hseqT store [t&1][col][1024] ---- */
    {
        float* hT2 = g_hseqT[t&1] + bm*64;
#pragma unroll
        for (int i = 0; i < 8; i++){
            int li = tid + i*256;          /* 2048 = 32 cols x 64 rows */
            int col = li >> 6, row = li & 63;
            hT2[(size_t)(h*32 + col)*1024 + row] = epi[row*33 + col];
        }
    }
    /* ---- pred partials for step t+1 ---- */
    if (tid < 64){
        int bg = bm*64 + tid;
        float px = 0.f, py = 0.f;
#pragma unroll
        for (int uu = 0; uu < 32; uu++){
            float hv = epi[tid*33 + uu];
            px = fmaf(hv, wo_s[2*uu],   px);
            py = fmaf(hv, wo_s[2*uu+1], py);
        }
        *(float2*)&g_predpart[t&1][((size_t)h*NBATCH + bg)*2] = make_float2(px, py);
    }
}

/* ================= Kernel 4: output head GEMM ================= */
__global__ void __launch_bounds__(256) out_kernel(
    const float* __restrict__ W_out, const float* __restrict__ b_out,
    const float* __restrict__ pitch, float* __restrict__ out)
{
    size_t r0 = (size_t)blockIdx.x * 64;
    int tid = threadIdx.x;
    int tx = tid & 15, ty = tid >> 4;

    __shared__ float a_s[32*68];
    __shared__ float w_s[32*96];

    float acc[4][6];
#pragma unroll
    for (int bi=0;bi<4;bi++)
#pragma unroll
        for (int ci=0;ci<6;ci++) acc[bi][ci]=0.f;

    for (int k0 = 0; k0 < 256; k0 += 32){
#pragma unroll
        for (int i = 0; i < 8; i++){
            int li = tid + i*256;
            int kk = li & 31, row = li >> 5;
            size_t r = r0 + row;
            int t = (int)(r % NSEQ), b = (int)(r / NSEQ);
            a_s[kk*68 + row] = g_hseq[((size_t)t*NBATCH + b)*256 + k0 + kk];
        }
#pragma unroll
        for (int i = 0; i < 12; i++){
            int li = tid + i*256;
            int n = li % 96, kk = li / 96;
            w_s[kk*96 + n] = (n < 90) ? W_out[(k0+kk)*90 + n] : 0.f;
        }
        __syncthreads();
#pragma unroll
        for (int kk = 0; kk < 32; kk++){
            float4 a = *(const float4*)&a_s[kk*68 + 4*ty];
            float w[6];
#pragma unroll
            for (int ci = 0; ci < 6; ci++) w[ci] = w_s[kk*96 + 6*tx + ci];
#pragma unroll
            for (int ci = 0; ci < 6; ci++){
                acc[0][ci] = fmaf(a.x, w[ci], acc[0][ci]);
                acc[1][ci] = fmaf(a.y, w[ci], acc[1][ci]);
                acc[2][ci] = fmaf(a.z, w[ci], acc[2][ci]);
                acc[3][ci] = fmaf(a.w, w[ci], acc[3][ci]);
            }
        }
        __syncthreads();
    }
#pragma unroll
    for (int bi = 0; bi < 4; bi++){
        size_t r = r0 + 4*ty + bi;
#pragma unroll
        for (int ci = 0; ci < 6; ci++){
            int n = 6*tx + ci;
            if (n < 90)
                out[r*90 + n] = (acc[bi][ci] + b_out[n]) * pitch[n & 1];
        }
    }
}

/* ================= host launcher ================= */
extern "C" void kernel_launch(void* const* d_in, const int* in_sizes, int n_in,
                              void* d_out, int out_size)
{
    const float* coords = (const float*)d_in[0];
    const float* pitch  = (const float*)d_in[1];
    const float* W_e1   = (const float*)d_in[2];
    const float* b_e1   = (const float*)d_in[3];
    const float* W_e2   = (const float*)d_in[4];
    const float* b_e2   = (const float*)d_in[5];
    const float* W_ih   = (const float*)d_in[6];
    const float* b_ih   = (const float*)d_in[7];
    const float* W_hh   = (const float*)d_in[8];
    const float* b_hh   = (const float*)d_in[9];
    const float* W_out  = (const float*)d_in[10];
    const float* b_out  = (const float*)d_in[11];
    float* out = (float*)d_out;

    size_t xpre_smem = 14592u * sizeof(float);                  /*  58,368 B */
    size_t rnn_smem  = (size_t)RNN_SMEM_FLOATS * sizeof(float); /* 226,304 B */
    static int attr_done = 0;
    if (!attr_done){
        cudaFuncSetAttribute(xpre_kernel, cudaFuncAttributeMaxDynamicSharedMemorySize,
                             (int)xpre_smem);
        cudaFuncSetAttribute(rnn_step_kernel, cudaFuncAttributeMaxDynamicSharedMemorySize,
                             (int)rnn_smem);
        attr_done = 1;
    }

    enc_kernel<<<NROWS/4, 256>>>(coords, W_e1, b_e1, W_e2, b_e2);
    xpre_kernel<<<dim3(16, NROWS/128), 256, xpre_smem>>>(coords, W_ih, b_ih, b_hh);

    for (int t = 0; t < NSEQ; t++)
        rnn_step_kernel<<<dim3(8,16), 256, rnn_smem>>>(
            coords, W_ih, W_hh, W_out, b_out, pitch, t);

    out_kernel<<<NROWS/64, 256>>>(W_out, b_out, pitch, out);
}

// round 9
// speedup vs baseline: 3.8950x; 1.0350x over previous
#include <cuda_runtime.h>
#include <math.h>

#define NBATCH 1024
#define NSEQ   200
#define NROWS  (NBATCH*NSEQ)   /* 204800 */

/* ------------ static scratch (no allocations allowed) ------------ */
__device__ float g_enc [NROWS*128];           /* encoder output                    */
__device__ float g_xpre[NROWS*1024];          /* gate preacts, [r][h8*128 + u*4+g] */
__device__ float g_hseq[NSEQ*NBATCH*256];     /* hx per step (output GEMM input)   */
__device__ float g_hseqT[2][256*NBATCH];      /* transposed hx, parity-buffered    */
__device__ float g_cx  [NBATCH*256];          /* cell state, thread-mapped         */
__device__ float g_predpart[2][8*NBATCH*2];   /* parity-buffered pred partials     */

typedef unsigned long long u64;

__device__ __forceinline__ u64 pack2(float lo, float hi){
    u64 r; asm("mov.b64 %0,{%1,%2};" : "=l"(r) : "f"(lo), "f"(hi)); return r;
}
__device__ __forceinline__ void unpack2(u64 v, float& lo, float& hi){
    asm("mov.b64 {%0,%1},%2;" : "=f"(lo), "=f"(hi) : "l"(v));
}
__device__ __forceinline__ u64 fma2(u64 a, u64 b, u64 c){
    u64 d; asm("fma.rn.f32x2 %0,%1,%2,%3;" : "=l"(d) : "l"(a), "l"(b), "l"(c)); return d;
}
__device__ __forceinline__ float sigmoidf_(float x){
    return __fdividef(1.0f, 1.0f + __expf(-x));
}

/* ================= Kernel 1: per-(b,t) set encoder ================= */
__global__ void enc_kernel(const float* __restrict__ coords,
                           const float* __restrict__ W_e1, const float* __restrict__ b_e1,
                           const float* __restrict__ W_e2, const float* __restrict__ b_e2)
{
    int rl = threadIdx.x >> 6;
    int j  = threadIdx.x & 63;
    size_t r = (size_t)blockIdx.x * 4 + rl;

    __shared__ float pt[4][44];
    __shared__ float m [4][2][64];

    if (j < 44) pt[rl][j] = coords[r*88 + ((j>>1)<<2) + (j&1)];
    __syncthreads();

    float w0 = W_e1[j], w1 = W_e1[64+j], bb = b_e1[j];
    float s1 = 0.f, s2 = 0.f;
#pragma unroll
    for (int p = 0; p < 11; p++){
        float hh = fmaf(pt[rl][2*p+1], w1, fmaf(pt[rl][2*p], w0, bb));
        s1 += fmaxf(hh, 0.f);
    }
#pragma unroll
    for (int p = 11; p < 22; p++){
        float hh = fmaf(pt[rl][2*p+1], w1, fmaf(pt[rl][2*p], w0, bb));
        s2 += fmaxf(hh, 0.f);
    }
    m[rl][0][j] = s1 * (1.0f/11.0f);
    m[rl][1][j] = s2 * (1.0f/11.0f);
    __syncthreads();

    float o1 = b_e2[j], o2 = b_e2[j];
#pragma unroll
    for (int k = 0; k < 64; k++){
        float w = W_e2[k*64 + j];
        o1 = fmaf(m[rl][0][k], w, o1);
        o2 = fmaf(m[rl][1][k], w, o2);
    }
    g_enc[r*128 + j]      = o1;
    g_enc[r*128 + 64 + j] = o2;
}

/* ================= Kernel 2: Xpre GEMM =================
   Output layout: g_xpre[r][h8*128 + u_local*4 + g], u_local 0..31.    */
__global__ void __launch_bounds__(256) xpre_kernel(
    const float* __restrict__ coords, const float* __restrict__ W_ih,
    const float* __restrict__ b_ih,   const float* __restrict__ b_hh)
{
    extern __shared__ float smx[];
    float* a_s = smx;            /* 32*132 = 4224 */
    float* w_s = a_s + 4224;     /* 32*64  = 2048 */
    float* epi = w_s + 2048;     /* 128*65 = 8320 */

    int h  = blockIdx.x;                 /* h16: 16 tiles of 16 units */
    size_t m0 = (size_t)blockIdx.y * 128;
    int tid = threadIdx.x;
    int tb = tid & 31, tu = tid >> 5;

    u64 acc2[4][4];
#pragma unroll
    for (int bi=0;bi<4;bi++)
#pragma unroll
        for (int g=0;g<4;g++) acc2[bi][g] = 0ULL;

    for (int k0 = 0; k0 < 172; k0 += 32){
#pragma unroll
        for (int i = 0; i < 16; i++){
            int li  = tid + i*256;
            int kk  = li & 31, row = li >> 5;
            int k   = k0 + kk;
            float v = 0.f;
            size_t r = m0 + row;
            if (k < 44)       v = coords[r*88 + ((k>>1)<<2) + (k&1)];
            else if (k < 172) v = g_enc[r*128 + (k-44)];
            a_s[kk*132 + row] = v;
        }
#pragma unroll
        for (int i = 0; i < 8; i++){
            int li = tid + i*256;
            int c  = li & 63, kk = li >> 6;
            int k  = k0 + kk;
            float v = 0.f;
            if (k < 172){
                int col = ((c>>4)<<8) + (h<<4) + (c&15);
                v = W_ih[k*1024 + col];
            }
            w_s[kk*64 + c] = v;
        }
        __syncthreads();
#pragma unroll
        for (int kk = 0; kk < 32; kk++){
            float4 a = *(const float4*)&a_s[kk*132 + 4*tb];
            u64 ax = pack2(a.x,a.x), ay = pack2(a.y,a.y);
            u64 az = pack2(a.z,a.z), aw = pack2(a.w,a.w);
            int kw = kk*64 + (tu<<1);
#pragma unroll
            for (int g = 0; g < 4; g++){
                u64 w2 = *(const u64*)&w_s[kw + g*16];
                acc2[0][g] = fma2(ax, w2, acc2[0][g]);
                acc2[1][g] = fma2(ay, w2, acc2[1][g]);
                acc2[2][g] = fma2(az, w2, acc2[2][g]);
                acc2[3][g] = fma2(aw, w2, acc2[3][g]);
            }
        }
        __syncthreads();
    }

#pragma unroll
    for (int g = 0; g < 4; g++){
        int col0 = (g<<8) + (h<<4) + 2*tu;
        float b0 = b_ih[col0]   + b_hh[col0];
        float b1 = b_ih[col0+1] + b_hh[col0+1];
#pragma unroll
        for (int bi = 0; bi < 4; bi++){
            float lo, hi; unpack2(acc2[bi][g], lo, hi);
            epi[(4*tb+bi)*65 + g*16 + 2*tu]     = lo + b0;
            epi[(4*tb+bi)*65 + g*16 + 2*tu + 1] = hi + b1;
        }
    }
    __syncthreads();
#pragma unroll
    for (int i = 0; i < 8; i++){
        int li = tid + i*256;            /* 2048 = 128 rows x 16 units */
        int row = li >> 4, j = li & 15;
        size_t r = m0 + row;
        int colp = (h>>1)*128 + ((h&1)*16 + j)*4;
        float4 v = make_float4(epi[row*65 +      j], epi[row*65 + 16 + j],
                               epi[row*65 + 32 + j], epi[row*65 + 48 + j]);
        *(float4*)&g_xpre[r*1024 + colp] = v;
    }
}

/* ================= Kernel 3: one recurrent step =================
   grid (8,16): h = 32-unit tile, bm = 64-row batch tile. 512 threads;
   thread (u=tid>>4, rb=tid&15): 4 rows x 1 unit x 4 gates.
   Per kk: 1 LDS.128 (a: 2 row-pairs) + 1 LDS.128 (w) + 4 movs + 8 fma2.
   4 warps/SMSP for latency hiding. Kernel boundary = global sync.     */
#define RNN_SMEM_FLOATS (32768 + 256*64 + 64 + 64 + 64 + 64)

__global__ void __launch_bounds__(512) rnn_step_kernel(
    const float* __restrict__ coords, const float* __restrict__ W_ih,
    const float* __restrict__ W_hh,   const float* __restrict__ W_out,
    const float* __restrict__ b_out,  const float* __restrict__ pitch, int t)
{
    extern __shared__ float sm[];
    float* w_s   = sm;                     /* [256][128] c=u*4+g : 32768 f */
    float* hx_s  = w_s + 32768;            /* [256][64]          : 16384 f */
    float* epi   = hx_s;                   /* overlay, [row*33+u]          */
    float* wo_s  = hx_s + 16384;           /* [32][2] */
    float* clo_s = wo_s + 64;
    float* px_s  = clo_s + 64;
    float* py_s  = px_s + 64;

    int h = blockIdx.x, bm = blockIdx.y;
    int tid = threadIdx.x;
    int u  = tid >> 4;                     /* unit 0..31      */
    int rb = tid & 15;                     /* row-block (x4)  */

    /* ---- per-launch: W_hh slice -> smem [k][u*4+g] ---- */
#pragma unroll
    for (int i = 0; i < 16; i++){
        int li = tid + i*512;              /* 8192 f4 = 256 k x 32 c4 */
        int k = li >> 5, c4 = li & 31;
        int g = c4 >> 3, u0 = (c4 & 7) * 4;
        float4 v = *(const float4*)&W_hh[k*1024 + g*256 + h*32 + u0];
        w_s[k*128 + (u0+0)*4 + g] = v.x;
        w_s[k*128 + (u0+1)*4 + g] = v.y;
        w_s[k*128 + (u0+2)*4 + g] = v.z;
        w_s[k*128 + (u0+3)*4 + g] = v.w;
    }
    if (tid < 64){
        int uu = tid >> 1, d = tid & 1;
        wo_s[tid] = W_out[((size_t)(h*32+uu))*90 + 88 + d];
    }
    float cw[3][4];
#pragma unroll
    for (int j = 0; j < 3; j++)
#pragma unroll
        for (int g = 0; g < 4; g++)
            cw[j][g] = W_ih[(172+j)*1024 + g*256 + h*32 + u];

    float ps0 = pitch[0], ps1 = pitch[1];
    float bo88 = b_out[88], bo89 = b_out[89];

    /* ---- pred + closest distance (per batch row) ---- */
    if (tid < 64){
        int bg = bm*64 + tid;
        float px = 0.f, py = 0.f;
        if (t > 0){
            const float* pp = g_predpart[(t-1)&1];
#pragma unroll
            for (int hh = 0; hh < 8; hh++){
                float2 v = __ldcg((const float2*)&pp[((size_t)hh*NBATCH + bg)*2]);
                px += v.x; py += v.y;
            }
            px = (px + bo88) * ps0;
            py = (py + bo89) * ps1;
        }
        const float* cp = coords + ((size_t)bg*NSEQ + t)*88;
        float md = 3.402823e38f;
#pragma unroll
        for (int p = 0; p < 22; p++){
            float dx = px - __ldg(&cp[4*p]), dy = py - __ldg(&cp[4*p+1]);
            md = fminf(md, fmaf(dx,dx,dy*dy));
        }
        clo_s[tid] = sqrtf(md);
        px_s[tid] = px; py_s[tid] = py;
    }

    u64 acc[2][4];
#pragma unroll
    for (int rp=0;rp<2;rp++)
#pragma unroll
        for (int g=0;g<4;g++) acc[rp][g] = 0ULL;

    if (t > 0){
        /* ---- stage hx (all K) from transposed buffer, coalesced ---- */
        const float* hT = g_hseqT[(t-1)&1] + bm*64;
#pragma unroll
        for (int i = 0; i < 16; i++){
            int li = tid + i*512;          /* 8192 f2 = 256 k x 32 pairs */
            int k = li >> 5, l = li & 31;
            float2 v = __ldcg((const float2*)&hT[k*1024 + 2*l]);
            *(float2*)&hx_s[k*64 + 2*l] = v;
        }
        __syncthreads();

        /* ---- GEMM: 256 kk ---- */
        const float* hbase = hx_s + rb*4;
        const float* wbase = w_s + u*4;
#pragma unroll 8
        for (int kk = 0; kk < 256; kk++){
            ulonglong2 A = *(const ulonglong2*)(hbase + kk*64);
            float4 wv = *(const float4*)(wbase + kk*128);
            u64 w0 = pack2(wv.x, wv.x), w1 = pack2(wv.y, wv.y);
            u64 w2 = pack2(wv.z, wv.z), w3 = pack2(wv.w, wv.w);
            acc[0][0] = fma2(A.x, w0, acc[0][0]);
            acc[0][1] = fma2(A.x, w1, acc[0][1]);
            acc[0][2] = fma2(A.x, w2, acc[0][2]);
            acc[0][3] = fma2(A.x, w3, acc[0][3]);
            acc[1][0] = fma2(A.y, w0, acc[1][0]);
            acc[1][1] = fma2(A.y, w1, acc[1][1]);
            acc[1][2] = fma2(A.y, w2, acc[1][2]);
            acc[1][3] = fma2(A.y, w3, acc[1][3]);
        }
    }
    __syncthreads();   /* hx_s reads done -> epi overlay is safe */

    /* ---- LSTM pointwise; cx streamed via thread-mapped global ---- */
    {
        size_t cxbase = ((size_t)((h*16 + bm)*512 + tid))*4;
        float cx[4];
        if (t > 0){
            float4 c0 = __ldcg((const float4*)&g_cx[cxbase]);
            cx[0]=c0.x; cx[1]=c0.y; cx[2]=c0.z; cx[3]=c0.w;
        } else {
#pragma unroll
            for (int r = 0; r < 4; r++) cx[r] = 0.f;
        }
#pragma unroll
        for (int r = 0; r < 4; r++){
            int row = rb*4 + r;
            size_t rglob = ((size_t)(bm*64 + row))*NSEQ + t;
            float4 xv = __ldcg((const float4*)&g_xpre[rglob*1024 + h*128 + u*4]);
            float clo = clo_s[row], ppx = px_s[row], ppy = py_s[row];
            float lo0, hi0, lo1, hi1, lo2, hi2, lo3, hi3;
            unpack2(acc[r>>1][0], lo0, hi0);
            unpack2(acc[r>>1][1], lo1, hi1);
            unpack2(acc[r>>1][2], lo2, hi2);
            unpack2(acc[r>>1][3], lo3, hi3);
            float gi = (r&1) ? hi0 : lo0;
            float gf = (r&1) ? hi1 : lo1;
            float gg = (r&1) ? hi2 : lo2;
            float go = (r&1) ? hi3 : lo3;
            gi += xv.x + clo*cw[0][0] + ppx*cw[1][0] + ppy*cw[2][0];
            gf += xv.y + clo*cw[0][1] + ppx*cw[1][1] + ppy*cw[2][1];
            gg += xv.z + clo*cw[0][2] + ppx*cw[1][2] + ppy*cw[2][2];
            go += xv.w + clo*cw[0][3] + ppx*cw[1][3] + ppy*cw[2][3];
            float c2 = sigmoidf_(gf)*cx[r] + sigmoidf_(gi)*tanhf(gg);
            float h2 = sigmoidf_(go)*tanhf(c2);
            cx[r] = c2;
            epi[row*33 + u] = h2;
        }
        *(float4*)&g_cx[cxbase] = make_float4(cx[0],cx[1],cx[2],cx[3]);
    }
    __syncthreads();

    /* ---- plain hseq store [t][b][256] ---- */
    {
        float* hout = g_hseq + ((size_t)t*NBATCH + bm*64)*256 + h*32;
#pragma unroll
        for (int i = 0; i < 4; i++){
            int li = tid + i*512;          /* 2048 = 64 rows x 32 c */
            int row = li >> 5, c = li & 31;
            hout[row*256 + c] = epi[row*33 + c];
        }
    }
    /* ---- transposed hseqT store [t&1][col][1024] ---- */
    {
        float* hT2 = g_hseqT[t&1] + bm*64;
#pragma unroll
        for (int i = 0; i < 4; i++){
            int li = tid + i*512;          /* 2048 = 32 cols x 64 rows */
            int col = li >> 6, row = li & 63;
            hT2[(size_t)(h*32 + col)*1024 + row] = epi[row*33 + col];
        }
    }
    /* ---- pred partials for step t+1 ---- */
    if (tid < 64){
        int bg = bm*64 + tid;
        float px = 0.f, py = 0.f;
#pragma unroll
        for (int uu = 0; uu < 32; uu++){
            float hv = epi[tid*33 + uu];
            px = fmaf(hv, wo_s[2*uu],   px);
            py = fmaf(hv, wo_s[2*uu+1], py);
        }
        *(float2*)&g_predpart[t&1][((size_t)h*NBATCH + bg)*2] = make_float2(px, py);
    }
}

/* ================= Kernel 4: output head GEMM ================= */
__global__ void __launch_bounds__(256) out_kernel(
    const float* __restrict__ W_out, const float* __restrict__ b_out,
    const float* __restrict__ pitch, float* __restrict__ out)
{
    size_t r0 = (size_t)blockIdx.x * 64;
    int tid = threadIdx.x;
    int tx = tid & 15, ty = tid >> 4;

    __shared__ float a_s[32*68];
    __shared__ float w_s[32*96];

    float acc[4][6];
#pragma unroll
    for (int bi=0;bi<4;bi++)
#pragma unroll
        for (int ci=0;ci<6;ci++) acc[bi][ci]=0.f;

    for (int k0 = 0; k0 < 256; k0 += 32){
#pragma unroll
        for (int i = 0; i < 8; i++){
            int li = tid + i*256;
            int kk = li & 31, row = li >> 5;
            size_t r = r0 + row;
            int t = (int)(r % NSEQ), b = (int)(r / NSEQ);
            a_s[kk*68 + row] = g_hseq[((size_t)t*NBATCH + b)*256 + k0 + kk];
        }
#pragma unroll
        for (int i = 0; i < 12; i++){
            int li = tid + i*256;
            int n = li % 96, kk = li / 96;
            w_s[kk*96 + n] = (n < 90) ? W_out[(k0+kk)*90 + n] : 0.f;
        }
        __syncthreads();
#pragma unroll
        for (int kk = 0; kk < 32; kk++){
            float4 a = *(const float4*)&a_s[kk*68 + 4*ty];
            float w[6];
#pragma unroll
            for (int ci = 0; ci < 6; ci++) w[ci] = w_s[kk*96 + 6*tx + ci];
#pragma unroll
            for (int ci = 0; ci < 6; ci++){
                acc[0][ci] = fmaf(a.x, w[ci], acc[0][ci]);
                acc[1][ci] = fmaf(a.y, w[ci], acc[1][ci]);
                acc[2][ci] = fmaf(a.z, w[ci], acc[2][ci]);
                acc[3][ci] = fmaf(a.w, w[ci], acc[3][ci]);
            }
        }
        __syncthreads();
    }
#pragma unroll
    for (int bi = 0; bi < 4; bi++){
        size_t r = r0 + 4*ty + bi;
#pragma unroll
        for (int ci = 0; ci < 6; ci++){
            int n = 6*tx + ci;
            if (n < 90)
                out[r*90 + n] = (acc[bi][ci] + b_out[n]) * pitch[n & 1];
        }
    }
}

/* ================= host launcher ================= */
extern "C" void kernel_launch(void* const* d_in, const int* in_sizes, int n_in,
                              void* d_out, int out_size)
{
    const float* coords = (const float*)d_in[0];
    const float* pitch  = (const float*)d_in[1];
    const float* W_e1   = (const float*)d_in[2];
    const float* b_e1   = (const float*)d_in[3];
    const float* W_e2   = (const float*)d_in[4];
    const float* b_e2   = (const float*)d_in[5];
    const float* W_ih   = (const float*)d_in[6];
    const float* b_ih   = (const float*)d_in[7];
    const float* W_hh   = (const float*)d_in[8];
    const float* b_hh   = (const float*)d_in[9];
    const float* W_out  = (const float*)d_in[10];
    const float* b_out  = (const float*)d_in[11];
    float* out = (float*)d_out;

    size_t xpre_smem = 14592u * sizeof(float);                  /*  58,368 B */
    size_t rnn_smem  = (size_t)RNN_SMEM_FLOATS * sizeof(float); /* 197,632 B */
    static int attr_done = 0;
    if (!attr_done){
        cudaFuncSetAttribute(xpre_kernel, cudaFuncAttributeMaxDynamicSharedMemorySize,
                             (int)xpre_smem);
        cudaFuncSetAttribute(rnn_step_kernel, cudaFuncAttributeMaxDynamicSharedMemorySize,
                             (int)rnn_smem);
        attr_done = 1;
    }

    enc_kernel<<<NROWS/4, 256>>>(coords, W_e1, b_e1, W_e2, b_e2);
    xpre_kernel<<<dim3(16, NROWS/128), 256, xpre_smem>>>(coords, W_ih, b_ih, b_hh);

    for (int t = 0; t < NSEQ; t++)
        rnn_step_kernel<<<dim3(8,16), 512, rnn_smem>>>(
            coords, W_ih, W_hh, W_out, b_out, pitch, t);

    out_kernel<<<NROWS/64, 256>>>(W_out, b_out, pitch, out);
}